// round 11
// baseline (speedup 1.0000x reference)
#include <cuda_runtime.h>
#include <stdint.h>

#define N_NODES 100000
#define N_EDGES 800000
#define HIDDEN  128

// ---------------- scratch (static device memory; no allocation) -------------
// Invariant: S1/S2/d1/d2 are ZERO at kernel_launch entry. True at module load;
// final_kernel re-zeroes the rows it consumed at the end of every call.
__device__ float g_S1[(size_t)N_NODES * HIDDEN];
__device__ float g_S2[(size_t)N_NODES * HIDDEN];
__device__ int   g_d1[N_NODES];
__device__ int   g_d2[N_NODES];

// ---------------- helpers ---------------------------------------------------
__device__ __forceinline__ unsigned long long pack2(float lo, float hi) {
    unsigned long long r;
    asm("mov.b64 %0, {%1, %2};" : "=l"(r) : "f"(lo), "f"(hi));
    return r;
}
__device__ __forceinline__ float2 unpack2(unsigned long long v) {
    float2 f;
    asm("mov.b64 {%0, %1}, %2;" : "=f"(f.x), "=f"(f.y) : "l"(v));
    return f;
}
__device__ __forceinline__ void fma2(unsigned long long& acc,
                                     unsigned long long a,
                                     unsigned long long b) {
    asm("fma.rn.f32x2 %0, %1, %2, %0;" : "+l"(acc) : "l"(a), "l"(b));
}

// ---------------- kernel 1: combined edge aggregation + self-term GEMM ------
// Grid: 1563*17 = 26571 blocks. bid%17==16 -> self-GEMM tile bid/17 (1563
// tiles); else edge block (25000 useful). Interleaving co-locates LTS-bound
// edge warps with fma-bound GEMM warps on the same SMs.
#define EDGE_BLOCKS 25000
#define GEMM_TILES  1563
#define GRID_COMBINED (GEMM_TILES * 17)

__global__ void __launch_bounds__(256)
combined_kernel(const float* __restrict__ h,
                const int*   __restrict__ esrc,
                const int*   __restrict__ edst,
                const float* __restrict__ Wsw,
                const float* __restrict__ Wsb,
                float* __restrict__ out) {
    __shared__ float As[32][68];
    __shared__ float Ws[32][132];

    const int bid = blockIdx.x;
    const int tid = threadIdx.x;

    if (bid % 17 != 16) {
        // ================= edge branch: 32 edges per block, 4 per warp ======
        int eblk = bid - bid / 17;
        if (eblk >= EDGE_BLOCKS) return;
        const int wid  = tid >> 5;
        const int lane = tid & 31;
        const int base = eblk * 32 + wid * 4;

        int s[4], d[4];
#pragma unroll
        for (int i = 0; i < 4; ++i) {
            s[i] = esrc[base + i];
            d[i] = edst[base + i];
        }
        float4 vd[4], vs[4];
#pragma unroll
        for (int i = 0; i < 4; ++i) {
            vd[i] = ((const float4*)(h + (size_t)d[i] * HIDDEN))[lane];
            vs[i] = ((const float4*)(h + (size_t)s[i] * HIDDEN))[lane];
        }
#pragma unroll
        for (int i = 0; i < 4; ++i) {
            atomicAdd(((float4*)(g_S1 + (size_t)s[i] * HIDDEN)) + lane, vd[i]);
            atomicAdd(((float4*)(g_S2 + (size_t)d[i] * HIDDEN)) + lane, vs[i]);
        }
        if (lane < 4)      atomicAdd(&g_d1[s[lane]], 1);
        else if (lane < 8) atomicAdd(&g_d2[d[lane - 4]], 1);
        return;
    }

    // ================= self-GEMM branch: out_partial = h@Wsw^T + Wsb ========
    const int tx   = tid & 31;
    const int ty   = tid >> 5;
    const int row0 = (bid / 17) * 64;

    int ar[2], ag[2], arow_ok[2];
#pragma unroll
    for (int j = 0; j < 2; ++j) {
        int lin = tid + j * 256;
        ar[j] = lin >> 3; ag[j] = lin & 7;
        arow_ok[j] = (row0 + ar[j]) < N_NODES;
    }
    int wc[4], wg[4];
#pragma unroll
    for (int j = 0; j < 4; ++j) {
        int lin = tid + j * 256;
        wc[j] = lin >> 3; wg[j] = lin & 7;
    }

    unsigned long long acc[4][4];
#pragma unroll
    for (int p = 0; p < 4; ++p)
#pragma unroll
        for (int c = 0; c < 4; ++c) acc[p][c] = 0ull;

    float4 pa[2], pw[4];
#pragma unroll
    for (int j = 0; j < 2; ++j) {
        pa[j] = make_float4(0.f, 0.f, 0.f, 0.f);
        if (arow_ok[j])
            pa[j] = *(const float4*)(h + (size_t)(row0 + ar[j]) * HIDDEN + ag[j] * 4);
    }
#pragma unroll
    for (int j = 0; j < 4; ++j)
        pw[j] = *(const float4*)(Wsw + (size_t)wc[j] * HIDDEN + wg[j] * 4);

#pragma unroll 1
    for (int chunk = 0; chunk < 4; ++chunk) {
        __syncthreads();
#pragma unroll
        for (int j = 0; j < 2; ++j) {
            int kk = ag[j] * 4, r = ar[j];
            As[kk + 0][r] = pa[j].x; As[kk + 1][r] = pa[j].y;
            As[kk + 2][r] = pa[j].z; As[kk + 3][r] = pa[j].w;
        }
#pragma unroll
        for (int j = 0; j < 4; ++j) {
            int kk = wg[j] * 4, c = wc[j];
            Ws[kk + 0][c] = pw[j].x; Ws[kk + 1][c] = pw[j].y;
            Ws[kk + 2][c] = pw[j].z; Ws[kk + 3][c] = pw[j].w;
        }
        __syncthreads();

        if (chunk < 3) {
            int k0 = (chunk + 1) * 32;
#pragma unroll
            for (int j = 0; j < 2; ++j) {
                pa[j] = make_float4(0.f, 0.f, 0.f, 0.f);
                if (arow_ok[j])
                    pa[j] = *(const float4*)(h + (size_t)(row0 + ar[j]) * HIDDEN + k0 + ag[j] * 4);
            }
#pragma unroll
            for (int j = 0; j < 4; ++j)
                pw[j] = *(const float4*)(Wsw + (size_t)wc[j] * HIDDEN + k0 + wg[j] * 4);
        }

#pragma unroll
        for (int kk = 0; kk < 32; ++kk) {
            ulonglong2 a01 = *(const ulonglong2*)&As[kk][ty * 8];
            ulonglong2 a23 = *(const ulonglong2*)&As[kk][ty * 8 + 4];
            float4 w = *(const float4*)&Ws[kk][tx * 4];
            unsigned long long w0 = pack2(w.x, w.x);
            unsigned long long w1 = pack2(w.y, w.y);
            unsigned long long w2 = pack2(w.z, w.z);
            unsigned long long w3 = pack2(w.w, w.w);
            fma2(acc[0][0], a01.x, w0); fma2(acc[0][1], a01.x, w1);
            fma2(acc[0][2], a01.x, w2); fma2(acc[0][3], a01.x, w3);
            fma2(acc[1][0], a01.y, w0); fma2(acc[1][1], a01.y, w1);
            fma2(acc[1][2], a01.y, w2); fma2(acc[1][3], a01.y, w3);
            fma2(acc[2][0], a23.x, w0); fma2(acc[2][1], a23.x, w1);
            fma2(acc[2][2], a23.x, w2); fma2(acc[2][3], a23.x, w3);
            fma2(acc[3][0], a23.y, w0); fma2(acc[3][1], a23.y, w1);
            fma2(acc[3][2], a23.y, w2); fma2(acc[3][3], a23.y, w3);
        }
    }

    const int colbase = tx * 4;
    float4 bs = *(const float4*)(Wsb + colbase);
#pragma unroll
    for (int p = 0; p < 4; ++p) {
        int re = row0 + ty * 8 + 2 * p;
        if (re >= N_NODES) break;
        float2 v0 = unpack2(acc[p][0]);
        float2 v1 = unpack2(acc[p][1]);
        float2 v2 = unpack2(acc[p][2]);
        float2 v3 = unpack2(acc[p][3]);
        {
            float4 o = make_float4(v0.x + bs.x, v1.x + bs.y, v2.x + bs.z, v3.x + bs.w);
            *(float4*)(out + (size_t)re * HIDDEN + colbase) = o;
        }
        int ro = re + 1;
        if (ro < N_NODES) {
            float4 o = make_float4(v0.y + bs.x, v1.y + bs.y, v2.y + bs.z, v3.y + bs.w);
            *(float4*)(out + (size_t)ro * HIDDEN + colbase) = o;
        }
    }
}

// ---------------- kernel 2: final GEMM (K=256 over S1/S2) + relu + re-zero --
__global__ void __launch_bounds__(256)
final_kernel(const float* __restrict__ Ww,
             const float* __restrict__ Wb,
             const float* __restrict__ Wtw,
             const float* __restrict__ Wtb,
             float* __restrict__ out) {
    __shared__ float As[32][68];
    __shared__ float Ws[32][132];

    const int tid = threadIdx.x;
    const int tx  = tid & 31;
    const int ty  = tid >> 5;
    const int row0 = blockIdx.x * 64;

    const float* Alist[2];
    Alist[0] = g_S1; Alist[1] = g_S2;
    const float* Wlist[2];
    Wlist[0] = Ww; Wlist[1] = Wtw;

    int ar[2], ag[2], arow_ok[2];
#pragma unroll
    for (int j = 0; j < 2; ++j) {
        int lin = tid + j * 256;
        ar[j] = lin >> 3; ag[j] = lin & 7;
        arow_ok[j] = (row0 + ar[j]) < N_NODES;
    }
    int wc[4], wg[4];
#pragma unroll
    for (int j = 0; j < 4; ++j) {
        int lin = tid + j * 256;
        wc[j] = lin >> 3; wg[j] = lin & 7;
    }

    unsigned long long acc[4][4];
#pragma unroll
    for (int p = 0; p < 4; ++p)
#pragma unroll
        for (int c = 0; c < 4; ++c) acc[p][c] = 0ull;

    float4 pa[2], pw[4];
#pragma unroll
    for (int j = 0; j < 2; ++j) {
        pa[j] = make_float4(0.f, 0.f, 0.f, 0.f);
        if (arow_ok[j])
            pa[j] = *(const float4*)(g_S1 + (size_t)(row0 + ar[j]) * HIDDEN + ag[j] * 4);
    }
#pragma unroll
    for (int j = 0; j < 4; ++j)
        pw[j] = *(const float4*)(Ww + (size_t)wc[j] * HIDDEN + wg[j] * 4);

#pragma unroll 1
    for (int chunk = 0; chunk < 8; ++chunk) {
        __syncthreads();
#pragma unroll
        for (int j = 0; j < 2; ++j) {
            int kk = ag[j] * 4, r = ar[j];
            As[kk + 0][r] = pa[j].x; As[kk + 1][r] = pa[j].y;
            As[kk + 2][r] = pa[j].z; As[kk + 3][r] = pa[j].w;
        }
#pragma unroll
        for (int j = 0; j < 4; ++j) {
            int kk = wg[j] * 4, c = wc[j];
            Ws[kk + 0][c] = pw[j].x; Ws[kk + 1][c] = pw[j].y;
            Ws[kk + 2][c] = pw[j].z; Ws[kk + 3][c] = pw[j].w;
        }
        __syncthreads();

        if (chunk < 7) {
            int nc   = chunk + 1;
            int sidx = nc >> 2;
            int k0   = (nc & 3) * 32;
            const float* A = Alist[sidx];
            const float* W = Wlist[sidx];
#pragma unroll
            for (int j = 0; j < 2; ++j) {
                pa[j] = make_float4(0.f, 0.f, 0.f, 0.f);
                if (arow_ok[j])
                    pa[j] = *(const float4*)(A + (size_t)(row0 + ar[j]) * HIDDEN + k0 + ag[j] * 4);
            }
#pragma unroll
            for (int j = 0; j < 4; ++j)
                pw[j] = *(const float4*)(W + (size_t)wc[j] * HIDDEN + k0 + wg[j] * 4);
        }

#pragma unroll
        for (int kk = 0; kk < 32; ++kk) {
            ulonglong2 a01 = *(const ulonglong2*)&As[kk][ty * 8];
            ulonglong2 a23 = *(const ulonglong2*)&As[kk][ty * 8 + 4];
            float4 w = *(const float4*)&Ws[kk][tx * 4];
            unsigned long long w0 = pack2(w.x, w.x);
            unsigned long long w1 = pack2(w.y, w.y);
            unsigned long long w2 = pack2(w.z, w.z);
            unsigned long long w3 = pack2(w.w, w.w);
            fma2(acc[0][0], a01.x, w0); fma2(acc[0][1], a01.x, w1);
            fma2(acc[0][2], a01.x, w2); fma2(acc[0][3], a01.x, w3);
            fma2(acc[1][0], a01.y, w0); fma2(acc[1][1], a01.y, w1);
            fma2(acc[1][2], a01.y, w2); fma2(acc[1][3], a01.y, w3);
            fma2(acc[2][0], a23.x, w0); fma2(acc[2][1], a23.x, w1);
            fma2(acc[2][2], a23.x, w2); fma2(acc[2][3], a23.x, w3);
            fma2(acc[3][0], a23.y, w0); fma2(acc[3][1], a23.y, w1);
            fma2(acc[3][2], a23.y, w2); fma2(acc[3][3], a23.y, w3);
        }
    }

    const int colbase = tx * 4;
    float4 bw = *(const float4*)(Wb  + colbase);
    float4 bt = *(const float4*)(Wtb + colbase);

#pragma unroll
    for (int p = 0; p < 4; ++p) {
        int re = row0 + ty * 8 + 2 * p;
        if (re >= N_NODES) break;
        float2 v0 = unpack2(acc[p][0]);
        float2 v1 = unpack2(acc[p][1]);
        float2 v2 = unpack2(acc[p][2]);
        float2 v3 = unpack2(acc[p][3]);
        {
            float f1 = (float)g_d1[re];
            float f2 = (float)g_d2[re];
            float4 pv = *(const float4*)(out + (size_t)re * HIDDEN + colbase);
            float4 o;
            o.x = fmaxf(pv.x + v0.x + f1 * bw.x + f2 * bt.x, 0.f);
            o.y = fmaxf(pv.y + v1.x + f1 * bw.y + f2 * bt.y, 0.f);
            o.z = fmaxf(pv.z + v2.x + f1 * bw.z + f2 * bt.z, 0.f);
            o.w = fmaxf(pv.w + v3.x + f1 * bw.w + f2 * bt.w, 0.f);
            *(float4*)(out + (size_t)re * HIDDEN + colbase) = o;
        }
        int ro = re + 1;
        if (ro < N_NODES) {
            float f1 = (float)g_d1[ro];
            float f2 = (float)g_d2[ro];
            float4 pv = *(const float4*)(out + (size_t)ro * HIDDEN + colbase);
            float4 o;
            o.x = fmaxf(pv.x + v0.y + f1 * bw.x + f2 * bt.x, 0.f);
            o.y = fmaxf(pv.y + v1.y + f1 * bw.y + f2 * bt.y, 0.f);
            o.z = fmaxf(pv.z + v2.y + f1 * bw.z + f2 * bt.z, 0.f);
            o.w = fmaxf(pv.w + v3.y + f1 * bw.w + f2 * bt.w, 0.f);
            *(float4*)(out + (size_t)ro * HIDDEN + colbase) = o;
        }
    }

    // ---- re-zero this block's rows of S1/S2 and degree counters (for the
    //      next call; rows are block-private so __syncthreads suffices) ----
    __syncthreads();
    float4 z = make_float4(0.f, 0.f, 0.f, 0.f);
#pragma unroll
    for (int i = 0; i < 8; ++i) {
        int idx = tid + i * 256;            // 0..2047 = 64 rows x 32 float4
        int r   = idx >> 5;
        int g   = idx & 31;
        int row = row0 + r;
        if (row < N_NODES) {
            ((float4*)(g_S1 + (size_t)row * HIDDEN))[g] = z;
            ((float4*)(g_S2 + (size_t)row * HIDDEN))[g] = z;
        }
    }
    if (tid < 64) {
        int row = row0 + tid;
        if (row < N_NODES) g_d1[row] = 0;
    } else if (tid < 128) {
        int row = row0 + tid - 64;
        if (row < N_NODES) g_d2[row] = 0;
    }
}

// ---------------- launch -----------------------------------------------------
extern "C" void kernel_launch(void* const* d_in, const int* in_sizes, int n_in,
                              void* d_out, int out_size) {
    const float* h    = (const float*)d_in[0];
    const int*   esrc = (const int*)  d_in[1];
    const int*   edst = (const int*)  d_in[2];
    const float* Ww   = (const float*)d_in[3];
    const float* Wb   = (const float*)d_in[4];
    const float* Wsw  = (const float*)d_in[5];
    const float* Wsb  = (const float*)d_in[6];
    const float* Wtw  = (const float*)d_in[7];
    const float* Wtb  = (const float*)d_in[8];
    float* out = (float*)d_out;

    combined_kernel<<<GRID_COMBINED, 256>>>(h, esrc, edst, Wsw, Wsb, out);
    final_kernel<<<GEMM_TILES, 256>>>(Ww, Wb, Wtw, Wtb, out);
}